// round 4
// baseline (speedup 1.0000x reference)
#include <cuda_runtime.h>
#include <cuda_bf16.h>
#include <math.h>

#define N_NODES 50000
#define N_EDGES 800000
#define D 128
#define N_GRAPHS 512
#define EPS 1e-5f

// ------------- scratch: device globals, ONLY touched from device code -------
__device__ float g_hA[N_NODES * D];
__device__ float g_hB[N_NODES * D];
__device__ float g_agg[N_NODES * D];
__device__ int   g_deg[N_NODES];
__device__ int   g_off[N_NODES + 1];
__device__ int   g_cur[N_NODES];
__device__ int   g_csr[N_EDGES];
__device__ float g_y4[N_NODES * 4];   // per-node: [Wl2 part (2) | Wr2 part (2)]
__device__ float g_h2[N_NODES * 2];
__device__ float g_psum[N_GRAPHS * 2];
__device__ float g_pmax[N_GRAPHS * 2];
__device__ int   g_pcnt[N_GRAPHS];
__device__ float g_WT[256 * 128];     // [k][j] pre-transposed concat [Wl^T ; Wr^T]
__device__ int   g_idx_is64;          // 1 if edge_index/batch are int64

// ------------- index dtype detection + safe index load ----------------------
__global__ void detect_dtype(const unsigned int* __restrict__ ei_raw) {
    // int64 little-endian indices < 2^31 have all high words == 0.
    // int32 data: "high word" slots are random node ids, nonzero w.h.p.
    int any = 0;
    for (int i = 0; i < 2048; i++)
        if (ei_raw[2 * i + 1] != 0u) any = 1;
    g_idx_is64 = any ? 0 : 1;
}

__device__ __forceinline__ int load_idx(const void* p, int i, int is64, int lim) {
    int v = is64 ? (int)((const long long*)p)[i] : ((const int*)p)[i];
    v = v < 0 ? 0 : v;
    return v >= lim ? lim - 1 : v;
}

// ---------------- init ----------------
__global__ void init_kernel() {
    int i = blockIdx.x * blockDim.x + threadIdx.x;
    if (i < N_NODES) g_deg[i] = 0;
    if (i < N_GRAPHS) {
        g_psum[i * 2] = 0.f; g_psum[i * 2 + 1] = 0.f;
        g_pmax[i * 2] = __int_as_float(0xff800000);
        g_pmax[i * 2 + 1] = __int_as_float(0xff800000);
        g_pcnt[i] = 0;
    }
}

// ---------------- CSR build ----------------
__global__ void count_deg(const void* __restrict__ ei) {
    int is64 = g_idx_is64;
    int e = blockIdx.x * blockDim.x + threadIdx.x;
    if (e < N_EDGES) {
        int d = load_idx(ei, N_EDGES + e, is64, N_NODES);
        atomicAdd(&g_deg[d], 1);
    }
}

__global__ void scan50k() {
    __shared__ int wsum[32];
    __shared__ int chunk_total;
    int tid = threadIdx.x, lane = tid & 31, wid = tid >> 5;
    int running = 0;
    for (int base = 0; base < N_NODES; base += 1024) {
        int i = base + tid;
        int v = (i < N_NODES) ? g_deg[i] : 0;
        int x = v;
        #pragma unroll
        for (int d = 1; d < 32; d <<= 1) {
            int y = __shfl_up_sync(0xffffffffu, x, d);
            if (lane >= d) x += y;
        }
        if (lane == 31) wsum[wid] = x;
        __syncthreads();
        if (wid == 0) {
            int s = wsum[lane];
            int t = s;
            #pragma unroll
            for (int d = 1; d < 32; d <<= 1) {
                int y = __shfl_up_sync(0xffffffffu, t, d);
                if (lane >= d) t += y;
            }
            wsum[lane] = t - s;               // exclusive warp offsets
            if (lane == 31) chunk_total = t;
        }
        __syncthreads();
        int excl = running + wsum[wid] + (x - v);
        if (i < N_NODES) { g_off[i] = excl; g_cur[i] = excl; }
        running += chunk_total;
        __syncthreads();
    }
    if (tid == 0) g_off[N_NODES] = running;
}

__global__ void csr_fill(const void* __restrict__ ei) {
    int is64 = g_idx_is64;
    int e = blockIdx.x * blockDim.x + threadIdx.x;
    if (e < N_EDGES) {
        int s = load_idx(ei, e, is64, N_NODES);
        int d = load_idx(ei, N_EDGES + e, is64, N_NODES);
        int slot = atomicAdd(&g_cur[d], 1);
        if (slot < N_EDGES) g_csr[slot] = s;
    }
}

// ------------- weight prep: g_WT[k][j] = [Wl^T ; Wr^T] ----------------------
__global__ void prep_w(const float* __restrict__ Wl, const float* __restrict__ Wr) {
    int i = blockIdx.x * blockDim.x + threadIdx.x;  // 256*128
    if (i < 256 * 128) {
        int k = i >> 7, j = i & 127;
        g_WT[i] = (k < 128) ? Wl[j * 128 + k] : Wr[j * 128 + (k - 128)];
    }
}

// ------------- mean aggregation: warp per node -> g_agg ---------------------
// src_sel: 0 = external x (param), 1 = g_hA
__global__ void spmm_mean(const float* __restrict__ x_ext, int src_sel) {
    const float* in = (src_sel == 0) ? x_ext : (const float*)g_hA;
    int warp = (blockIdx.x * blockDim.x + threadIdx.x) >> 5;
    int lane = threadIdx.x & 31;
    if (warp >= N_NODES) return;
    int s = g_off[warp], e = g_off[warp + 1];
    float4 acc = make_float4(0.f, 0.f, 0.f, 0.f);
    #pragma unroll 4
    for (int i = s; i < e; i++) {
        int j = g_csr[i];
        float4 v = *(const float4*)(in + (size_t)j * D + lane * 4);
        acc.x += v.x; acc.y += v.y; acc.z += v.z; acc.w += v.w;
    }
    int dg = e - s;
    float inv = 1.f / (float)(dg > 1 ? dg : 1);
    acc.x *= inv; acc.y *= inv; acc.z *= inv; acc.w *= inv;
    *(float4*)(g_agg + (size_t)warp * D + lane * 4) = acc;
}

// ---- fused GEMM: dst = g_agg@Wl^T + bl + root@Wr^T, then BN + ReLU ----------
// 64 nodes/block, 256 threads, k-tiled by 32. Static shared (~25.3KB).
// src_sel: 0 -> root = x_ext, dst = g_hA ; 1 -> root = g_hA, dst = g_hB
#define AS 33
#define BSS 132

__global__ void __launch_bounds__(256) gemm_sage(
    const float* __restrict__ x_ext,
    const float* __restrict__ bl,
    const float* __restrict__ bng, const float* __restrict__ bnb,
    const float* __restrict__ bnm, const float* __restrict__ bnv,
    int src_sel)
{
    __shared__ float As[64 * AS];    // 64 nodes x 32 k-slice
    __shared__ float Bs[32 * BSS];   // 32 k x 128 cols

    const float* root = (src_sel == 0) ? x_ext : (const float*)g_hA;
    float* out = (src_sel == 0) ? g_hA : g_hB;

    int tid = threadIdx.x;
    int base = blockIdx.x * 64;

    int lane = tid & 31, w = tid >> 5;
    int grp = lane >> 4;
    int col0 = (lane & 15) * 8;
    int nl0 = w * 8 + grp * 4;

    float acc[4][8];
    #pragma unroll
    for (int i = 0; i < 4; i++)
        #pragma unroll
        for (int c = 0; c < 8; c++) acc[i][c] = 0.f;

    for (int kt = 0; kt < 8; kt++) {
        const float* Asrc = (kt < 4) ? (const float*)g_agg : root;
        int ko = (kt & 3) * 32;
        // A slice: warp-contiguous 32-float row segments (coalesced)
        for (int l = tid; l < 64 * 32; l += 256) {
            int n = l >> 5, kk = l & 31;
            int gn = base + n;
            As[n * AS + kk] = (gn < N_NODES) ? Asrc[(size_t)gn * D + ko + kk] : 0.f;
        }
        // B slice: rows [kt*32, kt*32+32) of g_WT (coalesced)
        for (int l = tid; l < 32 * 128; l += 256) {
            int kk = l >> 7, j = l & 127;
            Bs[kk * BSS + j] = g_WT[(kt * 32 + kk) * 128 + j];
        }
        __syncthreads();
        #pragma unroll
        for (int kk = 0; kk < 32; kk++) {
            float4 b0 = *(const float4*)&Bs[kk * BSS + col0];
            float4 b1 = *(const float4*)&Bs[kk * BSS + col0 + 4];
            #pragma unroll
            for (int i = 0; i < 4; i++) {
                float a = As[(nl0 + i) * AS + kk];
                acc[i][0] += a * b0.x; acc[i][1] += a * b0.y;
                acc[i][2] += a * b0.z; acc[i][3] += a * b0.w;
                acc[i][4] += a * b1.x; acc[i][5] += a * b1.y;
                acc[i][6] += a * b1.z; acc[i][7] += a * b1.w;
            }
        }
        __syncthreads();
    }

    // epilogue: bias + BN + ReLU
    float blv[8], gv[8], bv[8], mv[8], sv[8];
    #pragma unroll
    for (int c = 0; c < 8; c++) {
        int j = col0 + c;
        blv[c] = bl[j];
        gv[c] = bng[j]; bv[c] = bnb[j]; mv[c] = bnm[j];
        sv[c] = rsqrtf(bnv[j] + EPS);
    }
    #pragma unroll
    for (int i = 0; i < 4; i++) {
        int gn = base + nl0 + i;
        if (gn >= N_NODES) continue;
        float v[8];
        #pragma unroll
        for (int c = 0; c < 8; c++) {
            float val = acc[i][c] + blv[c];
            val = (val - mv[c]) * sv[c] * gv[c] + bv[c];
            v[c] = fmaxf(val, 0.f);
        }
        float4* o = (float4*)(out + (size_t)gn * D + col0);
        o[0] = make_float4(v[0], v[1], v[2], v[3]);
        o[1] = make_float4(v[4], v[5], v[6], v[7]);
    }
}

// ------------- layer 3 (D_OUT=2): transform first, then aggregate ----------
__global__ void l3_transform(const float* __restrict__ Wl2,
                             const float* __restrict__ Wr2) {
    int warp = (blockIdx.x * blockDim.x + threadIdx.x) >> 5;
    int lane = threadIdx.x & 31;
    if (warp >= N_NODES) return;
    float4 x = *(const float4*)(g_hB + (size_t)warp * D + lane * 4);
    float p[4];
    #pragma unroll
    for (int o = 0; o < 4; o++) {
        const float* Wp = (o < 2) ? (Wl2 + o * 128) : (Wr2 + (o - 2) * 128);
        float4 wv = *(const float4*)(Wp + lane * 4);
        float s = x.x * wv.x + x.y * wv.y + x.z * wv.z + x.w * wv.w;
        #pragma unroll
        for (int d = 16; d; d >>= 1) s += __shfl_xor_sync(0xffffffffu, s, d);
        p[o] = s;
    }
    if (lane == 0) *(float4*)(g_y4 + warp * 4) = make_float4(p[0], p[1], p[2], p[3]);
}

__global__ void l3_aggregate(const float* __restrict__ bl2) {
    int n = blockIdx.x * blockDim.x + threadIdx.x;
    if (n >= N_NODES) return;
    int s = g_off[n], e = g_off[n + 1];
    float a0 = 0.f, a1 = 0.f;
    #pragma unroll 4
    for (int i = s; i < e; i++) {
        int j = g_csr[i];
        float2 v = *(const float2*)(g_y4 + j * 4);
        a0 += v.x; a1 += v.y;
    }
    int dg = e - s;
    float inv = 1.f / (float)(dg > 1 ? dg : 1);
    float2 r = *(const float2*)(g_y4 + n * 4 + 2);
    g_h2[n * 2 + 0] = a0 * inv + bl2[0] + r.x;
    g_h2[n * 2 + 1] = a1 * inv + bl2[1] + r.y;
}

// ---------------- pooling ----------------
__device__ __forceinline__ void atomicMaxF(float* addr, float v) {
    if (v >= 0.f) atomicMax((int*)addr, __float_as_int(v));
    else atomicMin((unsigned int*)addr, (unsigned int)__float_as_int(v));
}

__global__ void pool_kernel(const void* __restrict__ batch) {
    int is64 = g_idx_is64;
    int n = blockIdx.x * blockDim.x + threadIdx.x;
    if (n >= N_NODES) return;
    int g = load_idx(batch, n, is64, N_GRAPHS);
    float2 v = *(const float2*)(g_h2 + n * 2);
    atomicAdd(&g_psum[g * 2 + 0], v.x);
    atomicAdd(&g_psum[g * 2 + 1], v.y);
    atomicMaxF(&g_pmax[g * 2 + 0], v.x);
    atomicMaxF(&g_pmax[g * 2 + 1], v.y);
    atomicAdd(&g_pcnt[g], 1);
}

// ---------------- head MLP ----------------
__global__ void mlp_kernel(const float* __restrict__ mW1, const float* __restrict__ mb1,
                           const float* __restrict__ mW2, const float* __restrict__ mb2,
                           float* __restrict__ out) {
    __shared__ float gg[4];
    __shared__ float hid[128];
    int g = blockIdx.x, t = threadIdx.x;
    if (t < 2) {
        float c = (float)g_pcnt[g];
        float cc = c < 1.f ? 1.f : c;
        gg[t] = g_psum[g * 2 + t] / cc;
        gg[2 + t] = g_pmax[g * 2 + t];
    }
    __syncthreads();
    float s = mb1[t];
    #pragma unroll
    for (int c = 0; c < 4; c++) s += gg[c] * mW1[t * 4 + c];
    hid[t] = fmaxf(s, 0.f);
    __syncthreads();
    if (t < 2) {
        float o = mb2[t];
        #pragma unroll 8
        for (int j = 0; j < 128; j++) o += hid[j] * mW2[t * 128 + j];
        out[g * 2 + t] = o;
    }
}

// ---------------- launch (kernel launches only; no other CUDA APIs) --------
extern "C" void kernel_launch(void* const* d_in, const int* in_sizes, int n_in,
                              void* d_out, int out_size) {
    const float* x     = (const float*)d_in[0];
    const void*  ei    = d_in[1];
    const void*  batch = d_in[2];
    const float* Wl0 = (const float*)d_in[3];
    const float* bl0 = (const float*)d_in[4];
    const float* Wr0 = (const float*)d_in[5];
    const float* Wl1 = (const float*)d_in[6];
    const float* bl1 = (const float*)d_in[7];
    const float* Wr1 = (const float*)d_in[8];
    const float* Wl2 = (const float*)d_in[9];
    const float* bl2 = (const float*)d_in[10];
    const float* Wr2 = (const float*)d_in[11];
    const float* bn0g = (const float*)d_in[12];
    const float* bn0b = (const float*)d_in[13];
    const float* bn0m = (const float*)d_in[14];
    const float* bn0v = (const float*)d_in[15];
    const float* bn1g = (const float*)d_in[16];
    const float* bn1b = (const float*)d_in[17];
    const float* bn1m = (const float*)d_in[18];
    const float* bn1v = (const float*)d_in[19];
    const float* mW1 = (const float*)d_in[20];
    const float* mb1 = (const float*)d_in[21];
    const float* mW2 = (const float*)d_in[22];
    const float* mb2 = (const float*)d_in[23];
    float* out = (float*)d_out;

    const int EB = (N_EDGES + 255) / 256;           // 3125
    const int NB = (N_NODES + 255) / 256;           // 196
    const int WB = (N_NODES * 32 + 255) / 256;      // 6250 (warp per node)
    const int GB = (N_NODES + 63) / 64;             // 782

    detect_dtype<<<1, 1>>>((const unsigned int*)ei);
    init_kernel<<<NB, 256>>>();
    count_deg<<<EB, 256>>>(ei);
    scan50k<<<1, 1024>>>();
    csr_fill<<<EB, 256>>>(ei);

    // layer 0: agg(x) -> gemm -> g_hA
    prep_w<<<128, 256>>>(Wl0, Wr0);
    spmm_mean<<<WB, 256>>>(x, 0);
    gemm_sage<<<GB, 256>>>(x, bl0, bn0g, bn0b, bn0m, bn0v, 0);

    // layer 1: agg(g_hA) -> gemm -> g_hB
    prep_w<<<128, 256>>>(Wl1, Wr1);
    spmm_mean<<<WB, 256>>>(x, 1);
    gemm_sage<<<GB, 256>>>(x, bl1, bn1g, bn1b, bn1m, bn1v, 1);

    // layer 2 (D_OUT=2): transform-then-aggregate (linearity of mean agg)
    l3_transform<<<WB, 256>>>(Wl2, Wr2);
    l3_aggregate<<<NB, 256>>>(bl2);

    // pooling + head
    pool_kernel<<<NB, 256>>>(batch);
    mlp_kernel<<<N_GRAPHS, 128>>>(mW1, mb1, mW2, mb2, out);
}

// round 5
// speedup vs baseline: 1.1775x; 1.1775x over previous
#include <cuda_runtime.h>
#include <cuda_bf16.h>
#include <math.h>

#define N_NODES 50000
#define N_EDGES 800000
#define D 128
#define N_GRAPHS 512
#define EPS 1e-5f

// ------------- scratch: device globals, ONLY touched from device code -------
__device__ float g_hA[N_NODES * D];
__device__ float g_agg[N_NODES * D];
__device__ int   g_deg[N_NODES];
__device__ int   g_off[N_NODES];      // CSR range start (unordered assignment)
__device__ int   g_cur[N_NODES];
__device__ int   g_csr[N_EDGES];
__device__ int   g_total;
__device__ float g_y4[N_NODES * 4];   // per-node: [Wl2·h (2) | Wr2·h (2)]
__device__ float g_psum[N_GRAPHS * 2];
__device__ float g_pmax[N_GRAPHS * 2];
__device__ int   g_pcnt[N_GRAPHS];
__device__ float g_WT0[256 * 128];    // layer0: [k][j] concat [Wl^T ; Wr^T]
__device__ float g_WT1[256 * 128];    // layer1
__device__ int   g_idx_is64;

__device__ __forceinline__ int load_idx(const void* p, int i, int is64, int lim) {
    int v = is64 ? (int)((const long long*)p)[i] : ((const int*)p)[i];
    v = v < 0 ? 0 : v;
    return v >= lim ? lim - 1 : v;
}

// ---- setup: dtype detect + all inits + both weight transposes --------------
// grid: 256 blocks x 256 threads (65536 threads)
__global__ void setup_kernel(const unsigned int* __restrict__ ei_raw,
                             const float* __restrict__ Wl0, const float* __restrict__ Wr0,
                             const float* __restrict__ Wl1, const float* __restrict__ Wr1) {
    int idx = blockIdx.x * blockDim.x + threadIdx.x;

    // dtype detect: warp 0 of block 0 scans 4096 32-bit words as (lo,hi) pairs
    if (blockIdx.x == 0 && threadIdx.x < 32) {
        int any = 0;
        for (int i = threadIdx.x; i < 2048; i += 32)
            if (ei_raw[2 * i + 1] != 0u) any = 1;
        unsigned b = __ballot_sync(0xffffffffu, any);
        if (threadIdx.x == 0) { g_idx_is64 = b ? 0 : 1; g_total = 0; }
    }

    if (idx < N_NODES) g_deg[idx] = 0;
    if (idx < N_GRAPHS) {
        g_psum[idx * 2] = 0.f; g_psum[idx * 2 + 1] = 0.f;
        g_pmax[idx * 2] = __int_as_float(0xff800000);
        g_pmax[idx * 2 + 1] = __int_as_float(0xff800000);
        g_pcnt[idx] = 0;
    }
    // weight transposes: i in [0,32768) -> WT0 ; [32768,65536) -> WT1
    if (idx < 32768) {
        int k = idx >> 7, j = idx & 127;
        g_WT0[idx] = (k < 128) ? Wl0[j * 128 + k] : Wr0[j * 128 + (k - 128)];
    } else {
        int i2 = idx - 32768;
        int k = i2 >> 7, j = i2 & 127;
        g_WT1[i2] = (k < 128) ? Wl1[j * 128 + k] : Wr1[j * 128 + (k - 128)];
    }
}

// ---------------- CSR build ----------------
__global__ void count_deg(const void* __restrict__ ei) {
    int is64 = g_idx_is64;
    int e = blockIdx.x * blockDim.x + threadIdx.x;
    if (e < N_EDGES) {
        int d = load_idx(ei, N_EDGES + e, is64, N_NODES);
        atomicAdd(&g_deg[d], 1);
    }
}

// unordered offset assignment: warp-aggregated atomic (no global scan needed)
__global__ void assign_off() {
    int i = blockIdx.x * blockDim.x + threadIdx.x;
    int lane = threadIdx.x & 31;
    int v = (i < N_NODES) ? g_deg[i] : 0;
    int x = v;
    #pragma unroll
    for (int d = 1; d < 32; d <<= 1) {
        int y = __shfl_up_sync(0xffffffffu, x, d);
        if (lane >= d) x += y;
    }
    int tot = __shfl_sync(0xffffffffu, x, 31);
    int base = 0;
    if (lane == 31) base = atomicAdd(&g_total, tot);
    base = __shfl_sync(0xffffffffu, base, 31);
    if (i < N_NODES) {
        int off = base + x - v;
        g_off[i] = off;
        g_cur[i] = off;
    }
}

__global__ void csr_fill(const void* __restrict__ ei) {
    int is64 = g_idx_is64;
    int e = blockIdx.x * blockDim.x + threadIdx.x;
    if (e < N_EDGES) {
        int s = load_idx(ei, e, is64, N_NODES);
        int d = load_idx(ei, N_EDGES + e, is64, N_NODES);
        int slot = atomicAdd(&g_cur[d], 1);
        g_csr[slot] = s;
    }
}

// ------------- mean aggregation: warp per node -> g_agg ---------------------
__global__ void spmm_mean(const float* __restrict__ x_ext, int src_sel) {
    const float* in = (src_sel == 0) ? x_ext : (const float*)g_hA;
    int warp = (blockIdx.x * blockDim.x + threadIdx.x) >> 5;
    int lane = threadIdx.x & 31;
    if (warp >= N_NODES) return;
    int s = g_off[warp];
    int dg = g_deg[warp];
    int e = s + dg;
    float4 acc = make_float4(0.f, 0.f, 0.f, 0.f);
    #pragma unroll 4
    for (int i = s; i < e; i++) {
        int j = g_csr[i];
        float4 v = *(const float4*)(in + (size_t)j * D + lane * 4);
        acc.x += v.x; acc.y += v.y; acc.z += v.z; acc.w += v.w;
    }
    float inv = 1.f / (float)(dg > 1 ? dg : 1);
    acc.x *= inv; acc.y *= inv; acc.z *= inv; acc.w *= inv;
    *(float4*)(g_agg + (size_t)warp * D + lane * 4) = acc;
}

// ---- fused GEMM: h = relu(bn(agg@Wl^T + bl + root@Wr^T)) --------------------
// src_sel==0: root=x, write h -> g_hA.
// src_sel==1: root=g_hA, DON'T write h; instead emit y4 = [Wl2@h ; Wr2@h].
#define AS 33
#define BSS 132

__global__ void __launch_bounds__(256) gemm_sage(
    const float* __restrict__ x_ext,
    const float* __restrict__ bl,
    const float* __restrict__ bng, const float* __restrict__ bnb,
    const float* __restrict__ bnm, const float* __restrict__ bnv,
    const float* __restrict__ Wl2, const float* __restrict__ Wr2,
    int src_sel)
{
    __shared__ float As[64 * AS];
    __shared__ float Bs[32 * BSS];

    const float* root = (src_sel == 0) ? x_ext : (const float*)g_hA;
    const float* WT = (src_sel == 0) ? (const float*)g_WT0 : (const float*)g_WT1;

    int tid = threadIdx.x;
    int base = blockIdx.x * 64;

    int lane = tid & 31, w = tid >> 5;
    int grp = lane >> 4;
    int col0 = (lane & 15) * 8;
    int nl0 = w * 8 + grp * 4;

    float acc[4][8];
    #pragma unroll
    for (int i = 0; i < 4; i++)
        #pragma unroll
        for (int c = 0; c < 8; c++) acc[i][c] = 0.f;

    for (int kt = 0; kt < 8; kt++) {
        const float* Asrc = (kt < 4) ? (const float*)g_agg : root;
        int ko = (kt & 3) * 32;
        for (int l = tid; l < 64 * 32; l += 256) {
            int n = l >> 5, kk = l & 31;
            int gn = base + n;
            As[n * AS + kk] = (gn < N_NODES) ? Asrc[(size_t)gn * D + ko + kk] : 0.f;
        }
        for (int l = tid; l < 32 * 128; l += 256) {
            int kk = l >> 7, j = l & 127;
            Bs[kk * BSS + j] = WT[(kt * 32 + kk) * 128 + j];
        }
        __syncthreads();
        #pragma unroll
        for (int kk = 0; kk < 32; kk++) {
            float4 b0 = *(const float4*)&Bs[kk * BSS + col0];
            float4 b1 = *(const float4*)&Bs[kk * BSS + col0 + 4];
            #pragma unroll
            for (int i = 0; i < 4; i++) {
                float a = As[(nl0 + i) * AS + kk];
                acc[i][0] += a * b0.x; acc[i][1] += a * b0.y;
                acc[i][2] += a * b0.z; acc[i][3] += a * b0.w;
                acc[i][4] += a * b1.x; acc[i][5] += a * b1.y;
                acc[i][6] += a * b1.z; acc[i][7] += a * b1.w;
            }
        }
        __syncthreads();
    }

    // epilogue: bias + BN + ReLU
    float blv[8], gv[8], bv[8], mv[8], sv[8];
    #pragma unroll
    for (int c = 0; c < 8; c++) {
        int j = col0 + c;
        blv[c] = bl[j];
        gv[c] = bng[j]; bv[c] = bnb[j]; mv[c] = bnm[j];
        sv[c] = rsqrtf(bnv[j] + EPS);
    }

    if (src_sel == 0) {
        #pragma unroll
        for (int i = 0; i < 4; i++) {
            int gn = base + nl0 + i;
            if (gn >= N_NODES) continue;
            float v[8];
            #pragma unroll
            for (int c = 0; c < 8; c++) {
                float val = acc[i][c] + blv[c];
                val = (val - mv[c]) * sv[c] * gv[c] + bv[c];
                v[c] = fmaxf(val, 0.f);
            }
            float4* o = (float4*)(g_hA + (size_t)gn * D + col0);
            o[0] = make_float4(v[0], v[1], v[2], v[3]);
            o[1] = make_float4(v[4], v[5], v[6], v[7]);
        }
    } else {
        // fused layer-2 transform: y4 = [Wl2@h ; Wr2@h] per node
        float w2[4][8];
        #pragma unroll
        for (int o = 0; o < 4; o++) {
            const float* Wp = (o < 2) ? (Wl2 + o * 128) : (Wr2 + (o - 2) * 128);
            #pragma unroll
            for (int c = 0; c < 8; c++) w2[o][c] = __ldg(&Wp[col0 + c]);
        }
        #pragma unroll
        for (int i = 0; i < 4; i++) {
            float p0 = 0.f, p1 = 0.f, p2 = 0.f, p3 = 0.f;
            #pragma unroll
            for (int c = 0; c < 8; c++) {
                float val = acc[i][c] + blv[c];
                val = (val - mv[c]) * sv[c] * gv[c] + bv[c];
                val = fmaxf(val, 0.f);
                p0 += val * w2[0][c]; p1 += val * w2[1][c];
                p2 += val * w2[2][c]; p3 += val * w2[3][c];
            }
            // half-warp (16 lanes, same node) reduce
            #pragma unroll
            for (int d = 1; d < 16; d <<= 1) {
                p0 += __shfl_xor_sync(0xffffffffu, p0, d);
                p1 += __shfl_xor_sync(0xffffffffu, p1, d);
                p2 += __shfl_xor_sync(0xffffffffu, p2, d);
                p3 += __shfl_xor_sync(0xffffffffu, p3, d);
            }
            int gn = base + nl0 + i;
            if ((lane & 15) == 0 && gn < N_NODES)
                *(float4*)(g_y4 + gn * 4) = make_float4(p0, p1, p2, p3);
        }
    }
}

// ------- layer 3 aggregate + graph pooling (fused) --------------------------
__device__ __forceinline__ void atomicMaxF(float* addr, float v) {
    if (v >= 0.f) atomicMax((int*)addr, __float_as_int(v));
    else atomicMin((unsigned int*)addr, (unsigned int)__float_as_int(v));
}

__global__ void l3agg_pool(const float* __restrict__ bl2,
                           const void* __restrict__ batch) {
    int is64 = g_idx_is64;
    int n = blockIdx.x * blockDim.x + threadIdx.x;
    if (n >= N_NODES) return;
    int s = g_off[n];
    int dg = g_deg[n];
    int e = s + dg;
    float a0 = 0.f, a1 = 0.f;
    #pragma unroll 4
    for (int i = s; i < e; i++) {
        int j = g_csr[i];
        float2 v = *(const float2*)(g_y4 + j * 4);
        a0 += v.x; a1 += v.y;
    }
    float inv = 1.f / (float)(dg > 1 ? dg : 1);
    float2 r = *(const float2*)(g_y4 + n * 4 + 2);
    float v0 = a0 * inv + bl2[0] + r.x;
    float v1 = a1 * inv + bl2[1] + r.y;

    int g = load_idx(batch, n, is64, N_GRAPHS);
    atomicAdd(&g_psum[g * 2 + 0], v0);
    atomicAdd(&g_psum[g * 2 + 1], v1);
    atomicMaxF(&g_pmax[g * 2 + 0], v0);
    atomicMaxF(&g_pmax[g * 2 + 1], v1);
    atomicAdd(&g_pcnt[g], 1);
}

// ---------------- head MLP ----------------
__global__ void mlp_kernel(const float* __restrict__ mW1, const float* __restrict__ mb1,
                           const float* __restrict__ mW2, const float* __restrict__ mb2,
                           float* __restrict__ out) {
    __shared__ float gg[4];
    __shared__ float hid[128];
    int g = blockIdx.x, t = threadIdx.x;
    if (t < 2) {
        float c = (float)g_pcnt[g];
        float cc = c < 1.f ? 1.f : c;
        gg[t] = g_psum[g * 2 + t] / cc;
        gg[2 + t] = g_pmax[g * 2 + t];
    }
    __syncthreads();
    float s = mb1[t];
    #pragma unroll
    for (int c = 0; c < 4; c++) s += gg[c] * mW1[t * 4 + c];
    hid[t] = fmaxf(s, 0.f);
    __syncthreads();
    if (t < 2) {
        float o = mb2[t];
        #pragma unroll 8
        for (int j = 0; j < 128; j++) o += hid[j] * mW2[t * 128 + j];
        out[g * 2 + t] = o;
    }
}

// ---------------- launch (kernel launches only) -----------------------------
extern "C" void kernel_launch(void* const* d_in, const int* in_sizes, int n_in,
                              void* d_out, int out_size) {
    const float* x     = (const float*)d_in[0];
    const void*  ei    = d_in[1];
    const void*  batch = d_in[2];
    const float* Wl0 = (const float*)d_in[3];
    const float* bl0 = (const float*)d_in[4];
    const float* Wr0 = (const float*)d_in[5];
    const float* Wl1 = (const float*)d_in[6];
    const float* bl1 = (const float*)d_in[7];
    const float* Wr1 = (const float*)d_in[8];
    const float* Wl2 = (const float*)d_in[9];
    const float* bl2 = (const float*)d_in[10];
    const float* Wr2 = (const float*)d_in[11];
    const float* bn0g = (const float*)d_in[12];
    const float* bn0b = (const float*)d_in[13];
    const float* bn0m = (const float*)d_in[14];
    const float* bn0v = (const float*)d_in[15];
    const float* bn1g = (const float*)d_in[16];
    const float* bn1b = (const float*)d_in[17];
    const float* bn1m = (const float*)d_in[18];
    const float* bn1v = (const float*)d_in[19];
    const float* mW1 = (const float*)d_in[20];
    const float* mb1 = (const float*)d_in[21];
    const float* mW2 = (const float*)d_in[22];
    const float* mb2 = (const float*)d_in[23];
    float* out = (float*)d_out;

    const int EB = (N_EDGES + 255) / 256;           // 3125
    const int NB = (N_NODES + 255) / 256;           // 196
    const int WB = (N_NODES * 32 + 255) / 256;      // 6250 (warp per node)
    const int GB = (N_NODES + 63) / 64;             // 782

    setup_kernel<<<256, 256>>>((const unsigned int*)ei, Wl0, Wr0, Wl1, Wr1); // 1
    count_deg<<<EB, 256>>>(ei);                                              // 2
    assign_off<<<NB, 256>>>();                                               // 3
    csr_fill<<<EB, 256>>>(ei);                                               // 4

    // layer 0
    spmm_mean<<<WB, 256>>>(x, 0);                                            // 5
    gemm_sage<<<GB, 256>>>(x, bl0, bn0g, bn0b, bn0m, bn0v, Wl2, Wr2, 0);     // 6 <- profiled
    // layer 1 (+ fused layer-2 transform in epilogue)
    spmm_mean<<<WB, 256>>>(x, 1);                                            // 7
    gemm_sage<<<GB, 256>>>(x, bl1, bn1g, bn1b, bn1m, bn1v, Wl2, Wr2, 1);     // 8
    // layer 2 aggregate + pooling
    l3agg_pool<<<NB, 256>>>(bl2, batch);                                     // 9
    mlp_kernel<<<N_GRAPHS, 128>>>(mW1, mb1, mW2, mb2, out);                  // 10
}

// round 7
// speedup vs baseline: 1.7649x; 1.4989x over previous
#include <cuda_runtime.h>
#include <cuda_bf16.h>
#include <math.h>

#define N_NODES 50000
#define N_EDGES 800000
#define D 128
#define N_GRAPHS 512
#define EPS 1e-5f

// ------------- scratch: device globals, ONLY touched from device code -------
__device__ float g_hA[N_NODES * D];
__device__ float g_agg[N_NODES * D];
__device__ int   g_deg[N_NODES];
__device__ int   g_off[N_NODES];      // CSR range start (unordered assignment)
__device__ int   g_cur[N_NODES];
__device__ int   g_csr[N_EDGES];
__device__ int   g_total;
__device__ float g_y4[N_NODES * 4];   // per-node: [Wl2·h (2) | Wr2·h (2)]
__device__ float g_psum[N_GRAPHS * 2];
__device__ float g_pmax[N_GRAPHS * 2];
__device__ int   g_pcnt[N_GRAPHS];
__device__ float g_WT0[256 * 128];    // layer0: [k][j] concat [Wl^T ; Wr^T]
__device__ float g_WT1[256 * 128];    // layer1
__device__ int   g_idx_is64;

__device__ __forceinline__ int load_idx(const void* p, int i, int is64, int lim) {
    int v = is64 ? (int)((const long long*)p)[i] : ((const int*)p)[i];
    v = v < 0 ? 0 : v;
    return v >= lim ? lim - 1 : v;
}

// ---- setup: dtype detect + all inits + both weight transposes --------------
__global__ void setup_kernel(const unsigned int* __restrict__ ei_raw,
                             const float* __restrict__ Wl0, const float* __restrict__ Wr0,
                             const float* __restrict__ Wl1, const float* __restrict__ Wr1) {
    int idx = blockIdx.x * blockDim.x + threadIdx.x;

    if (blockIdx.x == 0 && threadIdx.x < 32) {
        int any = 0;
        for (int i = threadIdx.x; i < 2048; i += 32)
            if (ei_raw[2 * i + 1] != 0u) any = 1;
        unsigned b = __ballot_sync(0xffffffffu, any);
        if (threadIdx.x == 0) { g_idx_is64 = b ? 0 : 1; g_total = 0; }
    }

    if (idx < N_NODES) g_deg[idx] = 0;
    if (idx < N_GRAPHS) {
        g_psum[idx * 2] = 0.f; g_psum[idx * 2 + 1] = 0.f;
        g_pmax[idx * 2] = __int_as_float(0xff800000);
        g_pmax[idx * 2 + 1] = __int_as_float(0xff800000);
        g_pcnt[idx] = 0;
    }
    if (idx < 32768) {
        int k = idx >> 7, j = idx & 127;
        g_WT0[idx] = (k < 128) ? Wl0[j * 128 + k] : Wr0[j * 128 + (k - 128)];
    } else {
        int i2 = idx - 32768;
        int k = i2 >> 7, j = i2 & 127;
        g_WT1[i2] = (k < 128) ? Wl1[j * 128 + k] : Wr1[j * 128 + (k - 128)];
    }
}

// ---------------- CSR build ----------------
__global__ void count_deg(const void* __restrict__ ei) {
    int is64 = g_idx_is64;
    int e = blockIdx.x * blockDim.x + threadIdx.x;
    if (e < N_EDGES) {
        int d = load_idx(ei, N_EDGES + e, is64, N_NODES);
        atomicAdd(&g_deg[d], 1);
    }
}

__global__ void assign_off() {
    int i = blockIdx.x * blockDim.x + threadIdx.x;
    int lane = threadIdx.x & 31;
    int v = (i < N_NODES) ? g_deg[i] : 0;
    int x = v;
    #pragma unroll
    for (int d = 1; d < 32; d <<= 1) {
        int y = __shfl_up_sync(0xffffffffu, x, d);
        if (lane >= d) x += y;
    }
    int tot = __shfl_sync(0xffffffffu, x, 31);
    int base = 0;
    if (lane == 31) base = atomicAdd(&g_total, tot);
    base = __shfl_sync(0xffffffffu, base, 31);
    if (i < N_NODES) {
        int off = base + x - v;
        g_off[i] = off;
        g_cur[i] = off;
    }
}

__global__ void csr_fill(const void* __restrict__ ei) {
    int is64 = g_idx_is64;
    int e = blockIdx.x * blockDim.x + threadIdx.x;
    if (e < N_EDGES) {
        int s = load_idx(ei, e, is64, N_NODES);
        int d = load_idx(ei, N_EDGES + e, is64, N_NODES);
        int slot = atomicAdd(&g_cur[d], 1);
        g_csr[slot] = s;
    }
}

// ------------- mean aggregation: warp per node -> g_agg ---------------------
__global__ void spmm_mean(const float* __restrict__ x_ext, int src_sel) {
    const float* in = (src_sel == 0) ? x_ext : (const float*)g_hA;
    int warp = (blockIdx.x * blockDim.x + threadIdx.x) >> 5;
    int lane = threadIdx.x & 31;
    if (warp >= N_NODES) return;
    int s = g_off[warp];
    int dg = g_deg[warp];
    int e = s + dg;
    float4 acc = make_float4(0.f, 0.f, 0.f, 0.f);
    #pragma unroll 4
    for (int i = s; i < e; i++) {
        int j = g_csr[i];
        float4 v = *(const float4*)(in + (size_t)j * D + lane * 4);
        acc.x += v.x; acc.y += v.y; acc.z += v.z; acc.w += v.w;
    }
    float inv = 1.f / (float)(dg > 1 ? dg : 1);
    acc.x *= inv; acc.y *= inv; acc.z *= inv; acc.w *= inv;
    *(float4*)(g_agg + (size_t)warp * D + lane * 4) = acc;
}

// ---- fused GEMM: h = relu(bn(agg@Wl^T + bl + root@Wr^T)) --------------------
// 128x128 block tile, 8x8 thread tile, 256 threads, K=256 tiled by 32.
// src_sel==0: root=x, write h -> g_hA.
// src_sel==1: root=g_hA, emit y4 = [Wl2@h ; Wr2@h] (fused layer-2 transform).
#define AST 36    // As row stride (float4-aligned, conflict-free STS/LDS)
#define BST 132   // Bs row stride

__global__ void __launch_bounds__(256, 2) gemm_sage(
    const float* __restrict__ x_ext,
    const float* __restrict__ bl,
    const float* __restrict__ bng, const float* __restrict__ bnb,
    const float* __restrict__ bnm, const float* __restrict__ bnv,
    const float* __restrict__ Wl2, const float* __restrict__ Wr2,
    int src_sel)
{
    __shared__ float As[128 * AST];    // [row][k] 18.4KB
    __shared__ float Bs[32 * BST];     // [k][col] 16.9KB
    __shared__ float sScale[128], sShift[128];
    __shared__ float sW2[4 * 128];

    const float* root = (src_sel == 0) ? x_ext : (const float*)g_hA;
    const float* WT = (src_sel == 0) ? (const float*)g_WT0 : (const float*)g_WT1;

    int tid = threadIdx.x;
    int base = blockIdx.x * 128;
    int tr = tid >> 4, tc = tid & 15;
    int r0 = tr * 8, c0 = tc * 8;

    // fold bias+BN into scale/shift; stage FULL W2 (2x128 each of Wl2, Wr2)
    if (tid < 128) {
        float s = rsqrtf(bnv[tid] + EPS) * bng[tid];
        sScale[tid] = s;
        sShift[tid] = (bl[tid] - bnm[tid]) * s + bnb[tid];
    }
    for (int l = tid; l < 256; l += 256) {
        sW2[l] = Wl2[l];            // Wl2 rows 0,1 -> sW2[0..255]
        sW2[256 + l] = Wr2[l];      // Wr2 rows 0,1 -> sW2[256..511]
    }

    float acc[8][8];
    #pragma unroll
    for (int i = 0; i < 8; i++)
        #pragma unroll
        for (int j = 0; j < 8; j++) acc[i][j] = 0.f;

    for (int kt = 0; kt < 8; kt++) {
        const float* Asrc = (kt < 4) ? (const float*)g_agg : root;
        int ko = (kt & 3) * 32;
        // A tile: 128 rows x 32 k, coalesced float4 loads, conflict-free STS.128
        #pragma unroll
        for (int p = 0; p < 4; p++) {
            int row = (tid >> 3) + p * 32;
            int kq = (tid & 7) * 4;
            int gn = base + row;
            float4 v = (gn < N_NODES)
                ? *(const float4*)(Asrc + (size_t)gn * D + ko + kq)
                : make_float4(0.f, 0.f, 0.f, 0.f);
            *(float4*)&As[row * AST + kq] = v;
        }
        // B tile: 32 k x 128 cols, float4 coalesced
        #pragma unroll
        for (int l = tid; l < 1024; l += 256) {
            int kk = l >> 5, j4 = (l & 31) * 4;
            *(float4*)&Bs[kk * BST + j4] =
                *(const float4*)&WT[(kt * 32 + kk) * 128 + j4];
        }
        __syncthreads();

        #pragma unroll
        for (int k4 = 0; k4 < 8; k4++) {
            float4 a[8];
            #pragma unroll
            for (int i = 0; i < 8; i++)
                a[i] = *(float4*)&As[(r0 + i) * AST + k4 * 4];
            #pragma unroll
            for (int q = 0; q < 4; q++) {
                float4 b0 = *(float4*)&Bs[(k4 * 4 + q) * BST + c0];
                float4 b1 = *(float4*)&Bs[(k4 * 4 + q) * BST + c0 + 4];
                #pragma unroll
                for (int i = 0; i < 8; i++) {
                    float av = (q == 0) ? a[i].x : (q == 1) ? a[i].y
                             : (q == 2) ? a[i].z : a[i].w;
                    acc[i][0] += av * b0.x; acc[i][1] += av * b0.y;
                    acc[i][2] += av * b0.z; acc[i][3] += av * b0.w;
                    acc[i][4] += av * b1.x; acc[i][5] += av * b1.y;
                    acc[i][6] += av * b1.z; acc[i][7] += av * b1.w;
                }
            }
        }
        __syncthreads();
    }

    // epilogue
    float sc[8], sh[8];
    #pragma unroll
    for (int c = 0; c < 8; c++) { sc[c] = sScale[c0 + c]; sh[c] = sShift[c0 + c]; }

    if (src_sel == 0) {
        #pragma unroll
        for (int i = 0; i < 8; i++) {
            int gn = base + r0 + i;
            if (gn >= N_NODES) continue;
            float v[8];
            #pragma unroll
            for (int c = 0; c < 8; c++)
                v[c] = fmaxf(acc[i][c] * sc[c] + sh[c], 0.f);
            float4* o = (float4*)(g_hA + (size_t)gn * D + c0);
            o[0] = make_float4(v[0], v[1], v[2], v[3]);
            o[1] = make_float4(v[4], v[5], v[6], v[7]);
        }
    } else {
        float w2[4][8];
        #pragma unroll
        for (int o = 0; o < 4; o++)
            #pragma unroll
            for (int c = 0; c < 8; c++) w2[o][c] = sW2[o * 128 + c0 + c];
        int lane = tid & 31;
        #pragma unroll
        for (int i = 0; i < 8; i++) {
            float p0 = 0.f, p1 = 0.f, p2 = 0.f, p3 = 0.f;
            #pragma unroll
            for (int c = 0; c < 8; c++) {
                float val = fmaxf(acc[i][c] * sc[c] + sh[c], 0.f);
                p0 += val * w2[0][c]; p1 += val * w2[1][c];
                p2 += val * w2[2][c]; p3 += val * w2[3][c];
            }
            #pragma unroll
            for (int d = 1; d < 16; d <<= 1) {
                p0 += __shfl_xor_sync(0xffffffffu, p0, d);
                p1 += __shfl_xor_sync(0xffffffffu, p1, d);
                p2 += __shfl_xor_sync(0xffffffffu, p2, d);
                p3 += __shfl_xor_sync(0xffffffffu, p3, d);
            }
            int gn = base + r0 + i;
            if ((lane & 15) == 0 && gn < N_NODES)
                *(float4*)(g_y4 + gn * 4) = make_float4(p0, p1, p2, p3);
        }
    }
}

// ------- layer 3 aggregate + graph pooling (fused) --------------------------
__device__ __forceinline__ void atomicMaxF(float* addr, float v) {
    if (v >= 0.f) atomicMax((int*)addr, __float_as_int(v));
    else atomicMin((unsigned int*)addr, (unsigned int)__float_as_int(v));
}

__global__ void l3agg_pool(const float* __restrict__ bl2,
                           const void* __restrict__ batch) {
    int is64 = g_idx_is64;
    int n = blockIdx.x * blockDim.x + threadIdx.x;
    if (n >= N_NODES) return;
    int s = g_off[n];
    int dg = g_deg[n];
    int e = s + dg;
    float a0 = 0.f, a1 = 0.f;
    #pragma unroll 4
    for (int i = s; i < e; i++) {
        int j = g_csr[i];
        float2 v = *(const float2*)(g_y4 + j * 4);
        a0 += v.x; a1 += v.y;
    }
    float inv = 1.f / (float)(dg > 1 ? dg : 1);
    float2 r = *(const float2*)(g_y4 + n * 4 + 2);
    float v0 = a0 * inv + bl2[0] + r.x;
    float v1 = a1 * inv + bl2[1] + r.y;

    int g = load_idx(batch, n, is64, N_GRAPHS);
    atomicAdd(&g_psum[g * 2 + 0], v0);
    atomicAdd(&g_psum[g * 2 + 1], v1);
    atomicMaxF(&g_pmax[g * 2 + 0], v0);
    atomicMaxF(&g_pmax[g * 2 + 1], v1);
    atomicAdd(&g_pcnt[g], 1);
}

// ---------------- head MLP ----------------
__global__ void mlp_kernel(const float* __restrict__ mW1, const float* __restrict__ mb1,
                           const float* __restrict__ mW2, const float* __restrict__ mb2,
                           float* __restrict__ out) {
    __shared__ float gg[4];
    __shared__ float hid[128];
    int g = blockIdx.x, t = threadIdx.x;
    if (t < 2) {
        float c = (float)g_pcnt[g];
        float cc = c < 1.f ? 1.f : c;
        gg[t] = g_psum[g * 2 + t] / cc;
        gg[2 + t] = g_pmax[g * 2 + t];
    }
    __syncthreads();
    float s = mb1[t];
    #pragma unroll
    for (int c = 0; c < 4; c++) s += gg[c] * mW1[t * 4 + c];
    hid[t] = fmaxf(s, 0.f);
    __syncthreads();
    if (t < 2) {
        float o = mb2[t];
        #pragma unroll 8
        for (int j = 0; j < 128; j++) o += hid[j] * mW2[t * 128 + j];
        out[g * 2 + t] = o;
    }
}

// ---------------- launch (kernel launches only) -----------------------------
extern "C" void kernel_launch(void* const* d_in, const int* in_sizes, int n_in,
                              void* d_out, int out_size) {
    const float* x     = (const float*)d_in[0];
    const void*  ei    = d_in[1];
    const void*  batch = d_in[2];
    const float* Wl0 = (const float*)d_in[3];
    const float* bl0 = (const float*)d_in[4];
    const float* Wr0 = (const float*)d_in[5];
    const float* Wl1 = (const float*)d_in[6];
    const float* bl1 = (const float*)d_in[7];
    const float* Wr1 = (const float*)d_in[8];
    const float* Wl2 = (const float*)d_in[9];
    const float* bl2 = (const float*)d_in[10];
    const float* Wr2 = (const float*)d_in[11];
    const float* bn0g = (const float*)d_in[12];
    const float* bn0b = (const float*)d_in[13];
    const float* bn0m = (const float*)d_in[14];
    const float* bn0v = (const float*)d_in[15];
    const float* bn1g = (const float*)d_in[16];
    const float* bn1b = (const float*)d_in[17];
    const float* bn1m = (const float*)d_in[18];
    const float* bn1v = (const float*)d_in[19];
    const float* mW1 = (const float*)d_in[20];
    const float* mb1 = (const float*)d_in[21];
    const float* mW2 = (const float*)d_in[22];
    const float* mb2 = (const float*)d_in[23];
    float* out = (float*)d_out;

    const int EB = (N_EDGES + 255) / 256;           // 3125
    const int NB = (N_NODES + 255) / 256;           // 196
    const int WB = (N_NODES * 32 + 255) / 256;      // 6250 (warp per node)
    const int GB = (N_NODES + 127) / 128;           // 391

    setup_kernel<<<256, 256>>>((const unsigned int*)ei, Wl0, Wr0, Wl1, Wr1);
    count_deg<<<EB, 256>>>(ei);
    assign_off<<<NB, 256>>>();
    csr_fill<<<EB, 256>>>(ei);

    // layer 0
    spmm_mean<<<WB, 256>>>(x, 0);
    gemm_sage<<<GB, 256>>>(x, bl0, bn0g, bn0b, bn0m, bn0v, Wl2, Wr2, 0);
    // layer 1 (+ fused layer-2 transform in epilogue)
    spmm_mean<<<WB, 256>>>(x, 1);
    gemm_sage<<<GB, 256>>>(x, bl1, bn1g, bn1b, bn1m, bn1v, Wl2, Wr2, 1);
    // layer 2 aggregate + pooling
    l3agg_pool<<<NB, 256>>>(bl2, batch);
    mlp_kernel<<<N_GRAPHS, 128>>>(mW1, mb1, mW2, mb2, out);
}

// round 8
// speedup vs baseline: 1.8306x; 1.0373x over previous
#include <cuda_runtime.h>
#include <cuda_bf16.h>
#include <math.h>

#define N_NODES 50000
#define N_EDGES 800000
#define D 128
#define N_GRAPHS 512
#define EPS 1e-5f

// ------------- scratch: device globals, ONLY touched from device code -------
__device__ float g_hA[N_NODES * D];
__device__ float g_agg[N_NODES * D];
__device__ int   g_deg[N_NODES];
__device__ int   g_off[N_NODES];      // CSR range start (unordered assignment)
__device__ int   g_cur[N_NODES];
__device__ int   g_csr[N_EDGES];
__device__ int   g_total;
__device__ float g_y4[N_NODES * 4];   // per-node: [Wl2·h (2) | Wr2·h (2)]
__device__ float g_psum[N_GRAPHS * 2];
__device__ float g_pmax[N_GRAPHS * 2];
__device__ int   g_pcnt[N_GRAPHS];
__device__ float g_WT0[256 * 128];    // layer0: [k][j] concat [Wl^T ; Wr^T]
__device__ float g_WT1[256 * 128];    // layer1
__device__ int   g_idx_is64;

__device__ __forceinline__ int load_idx(const void* p, int i, int is64, int lim) {
    int v = is64 ? (int)((const long long*)p)[i] : ((const int*)p)[i];
    v = v < 0 ? 0 : v;
    return v >= lim ? lim - 1 : v;
}

// packed fp32x2 FMA (B300 FFMA2 — 2 fp32 MACs per fma-pipe issue slot)
#define FMA_F32X2(acc, a2, b2) \
    asm("fma.rn.f32x2 %0, %1, %2, %0;" : "+l"(acc) : "l"(a2), "l"(b2))
#define DUP_F32X2(dst, f) \
    asm("mov.b64 %0, {%1, %1};" : "=l"(dst) : "r"(__float_as_uint(f)))
#define UNPACK_F32X2_(lo, hi, p) \
    asm("mov.b64 {%0, %1}, %2;" : "=r"(lo), "=r"(hi) : "l"(p))

// ---- setup: dtype detect + all inits + both weight transposes --------------
__global__ void setup_kernel(const unsigned int* __restrict__ ei_raw,
                             const float* __restrict__ Wl0, const float* __restrict__ Wr0,
                             const float* __restrict__ Wl1, const float* __restrict__ Wr1) {
    int idx = blockIdx.x * blockDim.x + threadIdx.x;

    if (blockIdx.x == 0 && threadIdx.x < 32) {
        int any = 0;
        for (int i = threadIdx.x; i < 2048; i += 32)
            if (ei_raw[2 * i + 1] != 0u) any = 1;
        unsigned b = __ballot_sync(0xffffffffu, any);
        if (threadIdx.x == 0) { g_idx_is64 = b ? 0 : 1; g_total = 0; }
    }

    if (idx < N_NODES) g_deg[idx] = 0;
    if (idx < N_GRAPHS) {
        g_psum[idx * 2] = 0.f; g_psum[idx * 2 + 1] = 0.f;
        g_pmax[idx * 2] = __int_as_float(0xff800000);
        g_pmax[idx * 2 + 1] = __int_as_float(0xff800000);
        g_pcnt[idx] = 0;
    }
    if (idx < 32768) {
        int k = idx >> 7, j = idx & 127;
        g_WT0[idx] = (k < 128) ? Wl0[j * 128 + k] : Wr0[j * 128 + (k - 128)];
    } else {
        int i2 = idx - 32768;
        int k = i2 >> 7, j = i2 & 127;
        g_WT1[i2] = (k < 128) ? Wl1[j * 128 + k] : Wr1[j * 128 + (k - 128)];
    }
}

// ---------------- CSR build ----------------
__global__ void count_deg(const void* __restrict__ ei) {
    int is64 = g_idx_is64;
    int e = blockIdx.x * blockDim.x + threadIdx.x;
    if (e < N_EDGES) {
        int d = load_idx(ei, N_EDGES + e, is64, N_NODES);
        atomicAdd(&g_deg[d], 1);
    }
}

__global__ void assign_off() {
    int i = blockIdx.x * blockDim.x + threadIdx.x;
    int lane = threadIdx.x & 31;
    int v = (i < N_NODES) ? g_deg[i] : 0;
    int x = v;
    #pragma unroll
    for (int d = 1; d < 32; d <<= 1) {
        int y = __shfl_up_sync(0xffffffffu, x, d);
        if (lane >= d) x += y;
    }
    int tot = __shfl_sync(0xffffffffu, x, 31);
    int base = 0;
    if (lane == 31) base = atomicAdd(&g_total, tot);
    base = __shfl_sync(0xffffffffu, base, 31);
    if (i < N_NODES) {
        int off = base + x - v;
        g_off[i] = off;
        g_cur[i] = off;
    }
}

__global__ void csr_fill(const void* __restrict__ ei) {
    int is64 = g_idx_is64;
    int e = blockIdx.x * blockDim.x + threadIdx.x;
    if (e < N_EDGES) {
        int s = load_idx(ei, e, is64, N_NODES);
        int d = load_idx(ei, N_EDGES + e, is64, N_NODES);
        int slot = atomicAdd(&g_cur[d], 1);
        g_csr[slot] = s;
    }
}

// ------------- mean aggregation: warp per node -> g_agg ---------------------
__global__ void spmm_mean(const float* __restrict__ x_ext, int src_sel) {
    const float* in = (src_sel == 0) ? x_ext : (const float*)g_hA;
    int warp = (blockIdx.x * blockDim.x + threadIdx.x) >> 5;
    int lane = threadIdx.x & 31;
    if (warp >= N_NODES) return;
    int s = g_off[warp];
    int dg = g_deg[warp];
    int e = s + dg;
    float4 acc = make_float4(0.f, 0.f, 0.f, 0.f);
    #pragma unroll 4
    for (int i = s; i < e; i++) {
        int j = g_csr[i];
        float4 v = *(const float4*)(in + (size_t)j * D + lane * 4);
        acc.x += v.x; acc.y += v.y; acc.z += v.z; acc.w += v.w;
    }
    float inv = 1.f / (float)(dg > 1 ? dg : 1);
    acc.x *= inv; acc.y *= inv; acc.z *= inv; acc.w *= inv;
    *(float4*)(g_agg + (size_t)warp * D + lane * 4) = acc;
}

// ---- fused GEMM: h = relu(bn(agg@Wl^T + bl + root@Wr^T)) --------------------
// 128x128 block tile, 8x8 thread tile, 256 threads, K=256 tiled by 32.
// Inner product uses packed fp32x2 FFMA2 (2 MACs/issue).
// src_sel==0: root=x, write h -> g_hA.
// src_sel==1: root=g_hA, emit y4 = [Wl2@h ; Wr2@h] (fused layer-2 transform).
#define AST 36    // As row stride (float4-aligned, conflict-free STS/LDS)
#define BST 132   // Bs row stride

__global__ void __launch_bounds__(256, 2) gemm_sage(
    const float* __restrict__ x_ext,
    const float* __restrict__ bl,
    const float* __restrict__ bng, const float* __restrict__ bnb,
    const float* __restrict__ bnm, const float* __restrict__ bnv,
    const float* __restrict__ Wl2, const float* __restrict__ Wr2,
    int src_sel)
{
    __shared__ float As[128 * AST];    // [row][k] 18.4KB
    __shared__ float Bs[32 * BST];     // [k][col] 16.9KB
    __shared__ float sScale[128], sShift[128];
    __shared__ float sW2[4 * 128];

    const float* root = (src_sel == 0) ? x_ext : (const float*)g_hA;
    const float* WT = (src_sel == 0) ? (const float*)g_WT0 : (const float*)g_WT1;

    int tid = threadIdx.x;
    int base = blockIdx.x * 128;
    int tr = tid >> 4, tc = tid & 15;
    int r0 = tr * 8, c0 = tc * 8;

    // fold bias+BN into scale/shift; stage FULL W2 (2x128 each of Wl2, Wr2)
    if (tid < 128) {
        float s = rsqrtf(bnv[tid] + EPS) * bng[tid];
        sScale[tid] = s;
        sShift[tid] = (bl[tid] - bnm[tid]) * s + bnb[tid];
    }
    for (int l = tid; l < 256; l += 256) {
        sW2[l] = Wl2[l];
        sW2[256 + l] = Wr2[l];
    }

    // packed accumulators: acc2[i][p] = (C[i][2p], C[i][2p+1])
    unsigned long long acc2[8][4];
    #pragma unroll
    for (int i = 0; i < 8; i++)
        #pragma unroll
        for (int p = 0; p < 4; p++) acc2[i][p] = 0ULL;

    for (int kt = 0; kt < 8; kt++) {
        const float* Asrc = (kt < 4) ? (const float*)g_agg : root;
        int ko = (kt & 3) * 32;
        // A tile: 128 rows x 32 k, coalesced float4 loads, conflict-free STS.128
        #pragma unroll
        for (int p = 0; p < 4; p++) {
            int row = (tid >> 3) + p * 32;
            int kq = (tid & 7) * 4;
            int gn = base + row;
            float4 v = (gn < N_NODES)
                ? *(const float4*)(Asrc + (size_t)gn * D + ko + kq)
                : make_float4(0.f, 0.f, 0.f, 0.f);
            *(float4*)&As[row * AST + kq] = v;
        }
        // B tile: 32 k x 128 cols, float4 coalesced
        #pragma unroll
        for (int l = tid; l < 1024; l += 256) {
            int kk = l >> 5, j4 = (l & 31) * 4;
            *(float4*)&Bs[kk * BST + j4] =
                *(const float4*)&WT[(kt * 32 + kk) * 128 + j4];
        }
        __syncthreads();

        #pragma unroll
        for (int k4 = 0; k4 < 8; k4++) {
            float4 a[8];
            #pragma unroll
            for (int i = 0; i < 8; i++)
                a[i] = *(float4*)&As[(r0 + i) * AST + k4 * 4];
            #pragma unroll
            for (int q = 0; q < 4; q++) {
                // B row pairs: reinterpret 16B smem segments as packed f32x2
                const ulonglong2* brow =
                    (const ulonglong2*)&Bs[(k4 * 4 + q) * BST + c0];
                ulonglong2 bp0 = brow[0];   // (c0,c0+1),(c0+2,c0+3)
                ulonglong2 bp1 = brow[1];   // (c0+4,c0+5),(c0+6,c0+7)
                #pragma unroll
                for (int i = 0; i < 8; i++) {
                    float av = (q == 0) ? a[i].x : (q == 1) ? a[i].y
                             : (q == 2) ? a[i].z : a[i].w;
                    unsigned long long av2;
                    DUP_F32X2(av2, av);
                    FMA_F32X2(acc2[i][0], av2, bp0.x);
                    FMA_F32X2(acc2[i][1], av2, bp0.y);
                    FMA_F32X2(acc2[i][2], av2, bp1.x);
                    FMA_F32X2(acc2[i][3], av2, bp1.y);
                }
            }
        }
        __syncthreads();
    }

    // unpack accumulators
    float accf[8][8];
    #pragma unroll
    for (int i = 0; i < 8; i++)
        #pragma unroll
        for (int p = 0; p < 4; p++) {
            unsigned int lo, hi;
            UNPACK_F32X2_(lo, hi, acc2[i][p]);
            accf[i][2 * p] = __uint_as_float(lo);
            accf[i][2 * p + 1] = __uint_as_float(hi);
        }

    // epilogue
    float sc[8], sh[8];
    #pragma unroll
    for (int c = 0; c < 8; c++) { sc[c] = sScale[c0 + c]; sh[c] = sShift[c0 + c]; }

    if (src_sel == 0) {
        #pragma unroll
        for (int i = 0; i < 8; i++) {
            int gn = base + r0 + i;
            if (gn >= N_NODES) continue;
            float v[8];
            #pragma unroll
            for (int c = 0; c < 8; c++)
                v[c] = fmaxf(accf[i][c] * sc[c] + sh[c], 0.f);
            float4* o = (float4*)(g_hA + (size_t)gn * D + c0);
            o[0] = make_float4(v[0], v[1], v[2], v[3]);
            o[1] = make_float4(v[4], v[5], v[6], v[7]);
        }
    } else {
        float w2[4][8];
        #pragma unroll
        for (int o = 0; o < 4; o++)
            #pragma unroll
            for (int c = 0; c < 8; c++) w2[o][c] = sW2[o * 128 + c0 + c];
        int lane = tid & 31;
        #pragma unroll
        for (int i = 0; i < 8; i++) {
            float p0 = 0.f, p1 = 0.f, p2 = 0.f, p3 = 0.f;
            #pragma unroll
            for (int c = 0; c < 8; c++) {
                float val = fmaxf(accf[i][c] * sc[c] + sh[c], 0.f);
                p0 += val * w2[0][c]; p1 += val * w2[1][c];
                p2 += val * w2[2][c]; p3 += val * w2[3][c];
            }
            #pragma unroll
            for (int d = 1; d < 16; d <<= 1) {
                p0 += __shfl_xor_sync(0xffffffffu, p0, d);
                p1 += __shfl_xor_sync(0xffffffffu, p1, d);
                p2 += __shfl_xor_sync(0xffffffffu, p2, d);
                p3 += __shfl_xor_sync(0xffffffffu, p3, d);
            }
            int gn = base + r0 + i;
            if ((lane & 15) == 0 && gn < N_NODES)
                *(float4*)(g_y4 + gn * 4) = make_float4(p0, p1, p2, p3);
        }
    }
}

// ------- layer 3 aggregate + graph pooling (fused) --------------------------
__device__ __forceinline__ void atomicMaxF(float* addr, float v) {
    if (v >= 0.f) atomicMax((int*)addr, __float_as_int(v));
    else atomicMin((unsigned int*)addr, (unsigned int)__float_as_int(v));
}

__global__ void l3agg_pool(const float* __restrict__ bl2,
                           const void* __restrict__ batch) {
    int is64 = g_idx_is64;
    int n = blockIdx.x * blockDim.x + threadIdx.x;
    if (n >= N_NODES) return;
    int s = g_off[n];
    int dg = g_deg[n];
    int e = s + dg;
    float a0 = 0.f, a1 = 0.f;
    #pragma unroll 4
    for (int i = s; i < e; i++) {
        int j = g_csr[i];
        float2 v = *(const float2*)(g_y4 + j * 4);
        a0 += v.x; a1 += v.y;
    }
    float inv = 1.f / (float)(dg > 1 ? dg : 1);
    float2 r = *(const float2*)(g_y4 + n * 4 + 2);
    float v0 = a0 * inv + bl2[0] + r.x;
    float v1 = a1 * inv + bl2[1] + r.y;

    int g = load_idx(batch, n, is64, N_GRAPHS);
    atomicAdd(&g_psum[g * 2 + 0], v0);
    atomicAdd(&g_psum[g * 2 + 1], v1);
    atomicMaxF(&g_pmax[g * 2 + 0], v0);
    atomicMaxF(&g_pmax[g * 2 + 1], v1);
    atomicAdd(&g_pcnt[g], 1);
}

// ---------------- head MLP ----------------
__global__ void mlp_kernel(const float* __restrict__ mW1, const float* __restrict__ mb1,
                           const float* __restrict__ mW2, const float* __restrict__ mb2,
                           float* __restrict__ out) {
    __shared__ float gg[4];
    __shared__ float hid[128];
    int g = blockIdx.x, t = threadIdx.x;
    if (t < 2) {
        float c = (float)g_pcnt[g];
        float cc = c < 1.f ? 1.f : c;
        gg[t] = g_psum[g * 2 + t] / cc;
        gg[2 + t] = g_pmax[g * 2 + t];
    }
    __syncthreads();
    float s = mb1[t];
    #pragma unroll
    for (int c = 0; c < 4; c++) s += gg[c] * mW1[t * 4 + c];
    hid[t] = fmaxf(s, 0.f);
    __syncthreads();
    if (t < 2) {
        float o = mb2[t];
        #pragma unroll 8
        for (int j = 0; j < 128; j++) o += hid[j] * mW2[t * 128 + j];
        out[g * 2 + t] = o;
    }
}

// ---------------- launch (kernel launches only) -----------------------------
extern "C" void kernel_launch(void* const* d_in, const int* in_sizes, int n_in,
                              void* d_out, int out_size) {
    const float* x     = (const float*)d_in[0];
    const void*  ei    = d_in[1];
    const void*  batch = d_in[2];
    const float* Wl0 = (const float*)d_in[3];
    const float* bl0 = (const float*)d_in[4];
    const float* Wr0 = (const float*)d_in[5];
    const float* Wl1 = (const float*)d_in[6];
    const float* bl1 = (const float*)d_in[7];
    const float* Wr1 = (const float*)d_in[8];
    const float* Wl2 = (const float*)d_in[9];
    const float* bl2 = (const float*)d_in[10];
    const float* Wr2 = (const float*)d_in[11];
    const float* bn0g = (const float*)d_in[12];
    const float* bn0b = (const float*)d_in[13];
    const float* bn0m = (const float*)d_in[14];
    const float* bn0v = (const float*)d_in[15];
    const float* bn1g = (const float*)d_in[16];
    const float* bn1b = (const float*)d_in[17];
    const float* bn1m = (const float*)d_in[18];
    const float* bn1v = (const float*)d_in[19];
    const float* mW1 = (const float*)d_in[20];
    const float* mb1 = (const float*)d_in[21];
    const float* mW2 = (const float*)d_in[22];
    const float* mb2 = (const float*)d_in[23];
    float* out = (float*)d_out;

    const int EB = (N_EDGES + 255) / 256;           // 3125
    const int NB = (N_NODES + 255) / 256;           // 196
    const int WB = (N_NODES * 32 + 255) / 256;      // 6250 (warp per node)
    const int GB = (N_NODES + 127) / 128;           // 391

    setup_kernel<<<256, 256>>>((const unsigned int*)ei, Wl0, Wr0, Wl1, Wr1);
    count_deg<<<EB, 256>>>(ei);
    assign_off<<<NB, 256>>>();
    csr_fill<<<EB, 256>>>(ei);

    // layer 0
    spmm_mean<<<WB, 256>>>(x, 0);
    gemm_sage<<<GB, 256>>>(x, bl0, bn0g, bn0b, bn0m, bn0v, Wl2, Wr2, 0);
    // layer 1 (+ fused layer-2 transform in epilogue)
    spmm_mean<<<WB, 256>>>(x, 1);
    gemm_sage<<<GB, 256>>>(x, bl1, bn1g, bn1b, bn1m, bn1v, Wl2, Wr2, 1);
    // layer 2 aggregate + pooling
    l3agg_pool<<<NB, 256>>>(bl2, batch);
    mlp_kernel<<<N_GRAPHS, 128>>>(mW1, mb1, mW2, mb2, out);
}